// round 11
// baseline (speedup 1.0000x reference)
#include <cuda_runtime.h>

// HiPPO-LegS bilinear discretization + sequential scan, N=256, L=1024, ALPHA=0.5.
//
// With K = 2k, w_i = 1/(K+i+1), aK = 1:
//   u_i = (K-i) w_i,  diag_i = e_i/d_i = 2K w_i - 1,
//   Ad[i][j] = b_i * c_j * prod_{j<m<i} u_m  (i>j),  b_i = -r_i w_i,  c_j = 2K r_j w_j
//   Bd[i]    = 2 r_i w_i * prod_{m<i} u_m = -2 b_i G_i
// Per time step (t = k-1):
//   Z_{i+1} = u_i Z_i + v_i,  v_i = 2 r_i w_i (K c_i + f r_i),  Z_0 = 0
//   c'_i = u_i c_i + w_i (r_i (2f - Z_i) - c_i)
// Recurrence: systolic one-warp pipeline (lane l handles step t = beat - l,
// scalar Z and y-partial hop lanes via shfl_up).
// GBT: 64-thread blocks, thread owns 4 columns, one STG.128 per row,
// upper/diag handled branchlessly via W=0-until-activation + SELs.
//
// Output layout (flattened tuple): [c_all | y_all | GBT_A | GBT_B]

#define HP_L 1024
#define HP_N 256

#define OUT_C  0
#define OUT_Y  262144
#define OUT_GA 263168
#define OUT_GB 67372032

__global__ void __launch_bounds__(64) hippo_fused(
    const float* __restrict__ f,
    const float* __restrict__ init_state,
    const float* __restrict__ Bvec,
    float* __restrict__ out)
{
    __shared__ float4 s_pack[HP_N];              // GBT: {b_i, u_i, diag_i, -}
    float* s_f = reinterpret_cast<float*>(s_pack);  // block 0: f[0..1023] (same 4KB)

    const int tid = threadIdx.x;

    if (blockIdx.x == 0) {
        // -------- systolic recurrence + y: warp 0 only --------
        #pragma unroll
        for (int q = 0; q < HP_L / 64; q++) s_f[tid + 64 * q] = f[tid + 64 * q];
        __syncthreads();
        const int lane = tid;
        if (lane < 32) {
            float c[8], r[8], fi[8], fi1[8];
            #pragma unroll
            for (int e = 0; e < 8; e++) {
                int i = lane * 8 + e;
                r[e]   = Bvec[i];            // r_i = sqrt(2i+1)
                c[e]   = init_state[i];
                fi[e]  = (float)i;
                fi1[e] = (float)(i + 1);
            }
            float* out_c = out + OUT_C;
            float* out_y = out + OUT_Y;

            float Zreg = 0.0f, Yreg = 0.0f;
            float Kf = (float)(2 * (1 - lane));      // K = 2(b - lane + 1)

            for (int b = 0; b < HP_L + 31; b++) {
                float Zin = __shfl_up_sync(0xffffffffu, Zreg, 1);
                float yin = __shfl_up_sync(0xffffffffu, Yreg, 1);
                if (lane == 0) { Zin = 0.0f; yin = 0.0f; }

                const int t = b - lane;
                if (0 <= t && t < HP_L) {
                    const float fv = s_f[t];
                    const float f2 = fv + fv;        // 2f = hK

                    float Zl = Zin, ysum = 0.0f;
                    #pragma unroll
                    for (int e = 0; e < 8; e++) {
                        float w  = __frcp_rn(Kf + fi1[e]);               // 1/(K+i+1)
                        float u  = (Kf - fi[e]) * w;                     // (K-i)w
                        float fr = fv * r[e];
                        float v  = (2.0f * r[e] * w) * fmaf(Kf, c[e], fr);
                        float q2 = fmaf(r[e], f2 - Zl, -c[e]);           // r(2f-Z)-c
                        float x  = fmaf(u, c[e], w * q2);
                        Zl = fmaf(u, Zl, v);
                        c[e] = x;
                        ysum += x;
                    }
                    Zreg = Zl;
                    Yreg = yin + ysum;

                    float4* co = reinterpret_cast<float4*>(out_c + (size_t)t * HP_N + lane * 8);
                    co[0] = make_float4(c[0], c[1], c[2], c[3]);
                    co[1] = make_float4(c[4], c[5], c[6], c[7]);
                    if (lane == 31) out_y[t] = Yreg;
                }
                Kf += 2.0f;
            }
        }
        return;
    }

    // -------- GBT_A / GBT_B for k = blockIdx.x --------
    const int   k  = blockIdx.x;                 // 1..1024
    const float Kf = (float)(2 * k);             // K = 2k
    const float K2 = Kf + Kf;                    // 2K

    // per-block tables: b_i = -r_i w_i, u_i = (K-i) w_i, diag_i = 2K w_i - 1
    #pragma unroll
    for (int q = 0; q < HP_N / 64; q++) {
        int i = tid + 64 * q;
        float fi = (float)i;
        float w  = __frcp_rn(Kf + fi + 1.0f);
        float ri = Bvec[i];
        s_pack[i] = make_float4(-ri * w, (Kf - fi) * w, fmaf(K2, w, -1.0f), 0.0f);
    }
    __syncthreads();

    // this thread's 4 columns j = 4*tid .. 4*tid+3 : c_j = 2K r_j w_j
    float4 cj;
    {
        float4 r4 = reinterpret_cast<const float4*>(Bvec)[tid];
        float j0 = (float)(4 * tid);
        cj.x = K2 * r4.x * __frcp_rn(Kf + j0 + 1.0f);
        cj.y = K2 * r4.y * __frcp_rn(Kf + j0 + 2.0f);
        cj.z = K2 * r4.z * __frcp_rn(Kf + j0 + 3.0f);
        cj.w = K2 * r4.w * __frcp_rn(Kf + j0 + 4.0f);
    }

    float4* ga = reinterpret_cast<float4*>(out + OUT_GA + (size_t)(k - 1) * (HP_N * HP_N));
    float*  gb = out + OUT_GB + (size_t)(k - 1) * HP_N;

    float4 W = make_float4(0.0f, 0.0f, 0.0f, 0.0f);  // 0 until activation at i==j
    float  G = 1.0f;                                  // thread 0: prod_{m<i} u_m
    const int rb = -4 * tid;                          // rel = i - 4*tid

    #pragma unroll 8
    for (int i = 0; i < HP_N; i++) {
        float4 p = s_pack[i];                 // b_i, u_i, diag_i
        int rel = i + rb;

        float4 v;
        v.x = (p.x * cj.x) * W.x;  if (rel == 0) v.x = p.z;
        v.y = (p.x * cj.y) * W.y;  if (rel == 1) v.y = p.z;
        v.z = (p.x * cj.z) * W.z;  if (rel == 2) v.z = p.z;
        v.w = (p.x * cj.w) * W.w;  if (rel == 3) v.w = p.z;
        ga[(size_t)i * (HP_N / 4) + tid] = v;

        W.x *= p.y;  if (rel == 0) W.x = 1.0f;
        W.y *= p.y;  if (rel == 1) W.y = 1.0f;
        W.z *= p.y;  if (rel == 2) W.z = 1.0f;
        W.w *= p.y;  if (rel == 3) W.w = 1.0f;

        if (tid == 0) { gb[i] = -2.0f * p.x * G; G *= p.y; }  // 2 r_i w_i G
    }
}

extern "C" void kernel_launch(void* const* d_in, const int* in_sizes, int n_in,
                              void* d_out, int out_size) {
    const float* f  = (const float*)d_in[0];   // (L,1)
    const float* s0 = (const float*)d_in[1];   // (N,1) init_state
    // d_in[2] = A (unused: closed-form), d_in[3] = B = r
    const float* Bv = (const float*)d_in[3];
    float* out = (float*)d_out;

    // Single fused launch: block 0 = systolic recurrence + y on one warp;
    // blocks 1..1024 stream GBT_A/GBT_B (4 cols/thread, STG.128 per row).
    hippo_fused<<<1025, 64>>>(f, s0, Bv, out);
}